// round 3
// baseline (speedup 1.0000x reference)
#include <cuda_runtime.h>
#include <math.h>

#define TT 1500
#define BB 16
#define FF 440
#define HH 512
#define MM (TT*BB)      // 24000
#define NC 128          // persistent recurrence CTAs (single wave on 148 SMs)

// ---------------- device scratch (no allocations allowed) -------------------
__device__ float g_wh0[MM*HH];
__device__ float g_wz0[MM*HH];
__device__ float g_wh1[MM*HH];
__device__ float g_wz1[MM*HH];
__device__ float g_h1 [MM*HH];
__device__ float g_hbuf[2*BB*HH];
__device__ unsigned g_slots[NC];   // zero-init; monotonic across runs

// ---------------- sync helpers ---------------------------------------------
__device__ __forceinline__ unsigned ld_acq(const unsigned* p) {
    unsigned v;
    asm volatile("ld.acquire.gpu.u32 %0, [%1];" : "=r"(v) : "l"(p) : "memory");
    return v;
}
__device__ __forceinline__ void st_rel(unsigned* p, unsigned v) {
    asm volatile("st.release.gpu.u32 [%0], %1;" :: "l"(p), "r"(v) : "memory");
}

// ---------------- projection GEMM: C[M,512] = A[M,K] @ W[512,K]^T + bias ----
// 64x64 tile, BK=8, 256 threads, 4x4 micro-tile.
__global__ void __launch_bounds__(256) gemm512(
    const float* __restrict__ Aext, int a_is_h1,
    const float* __restrict__ W, const float* __restrict__ bias,
    int out_sel, int K)
{
    const float* A = a_is_h1 ? g_h1 : Aext;
    float* C = (out_sel == 0) ? g_wh0 : (out_sel == 1) ? g_wz0
             : (out_sel == 2) ? g_wh1 : g_wz1;

    __shared__ __align__(16) float As[8][64];
    __shared__ __align__(16) float Bs[8][64];

    int tid = threadIdx.x;
    int m0 = blockIdx.x * 64, n0 = blockIdx.y * 64;
    int lr = tid >> 2;            // 0..63
    int lk = (tid & 3) * 2;       // 0,2,4,6
    const float* ap = A + (size_t)(m0 + lr) * K + lk;
    const float* wp = W + (size_t)(n0 + lr) * K + lk;
    int ty = tid >> 4, tx = tid & 15;

    float acc[4][4] = {};
    int nkb = K / 8;
    for (int kb = 0; kb < nkb; ++kb) {
        float2 av = *(const float2*)ap;
        float2 wv = *(const float2*)wp;
        ap += 8; wp += 8;
        As[lk][lr] = av.x; As[lk+1][lr] = av.y;
        Bs[lk][lr] = wv.x; Bs[lk+1][lr] = wv.y;
        __syncthreads();
        #pragma unroll
        for (int k = 0; k < 8; ++k) {
            float4 a4 = *(const float4*)&As[k][ty*4];
            float4 b4 = *(const float4*)&Bs[k][tx*4];
            float a_[4] = {a4.x, a4.y, a4.z, a4.w};
            float b_[4] = {b4.x, b4.y, b4.z, b4.w};
            #pragma unroll
            for (int i = 0; i < 4; ++i)
                #pragma unroll
                for (int j = 0; j < 4; ++j)
                    acc[i][j] += a_[i] * b_[j];
        }
        __syncthreads();
    }
    #pragma unroll
    for (int i = 0; i < 4; ++i) {
        float4 o;
        o.x = acc[i][0] + bias[n0 + tx*4 + 0];
        o.y = acc[i][1] + bias[n0 + tx*4 + 1];
        o.z = acc[i][2] + bias[n0 + tx*4 + 2];
        o.w = acc[i][3] + bias[n0 + tx*4 + 3];
        *(float4*)&C[(size_t)(m0 + ty*4 + i) * HH + n0 + tx*4] = o;
    }
}

// ---------------- persistent recurrence kernel ------------------------------
// 128 CTAs x 256 threads. CTA owns 4 output columns (both gates).
// warp w: bg = w>>1 (batch group of 4), rg = w&1 (0: z-gate/Uz, 1: hcand/Uh).
// lane owns k = lane + 32*i (i<16); U slice in registers; h in smem.
__global__ void __launch_bounds__(256, 1) recur(
    const float* __restrict__ Uh, const float* __restrict__ Uz,
    int layer, float* __restrict__ out_ext)
{
    const float* wh = layer ? g_wh1 : g_wh0;
    const float* wz = layer ? g_wz1 : g_wz0;
    float* out = out_ext ? out_ext : g_h1;

    __shared__ __align__(16) float hs[BB][HH];   // 32 KB
    __shared__ float sdot[2][BB][4];
    __shared__ unsigned s_base;

    int tid  = threadIdx.x;
    int w    = tid >> 5, lane = tid & 31;
    int bg   = w >> 1,   rg   = w & 1;
    int j0   = blockIdx.x * 4;

    if (tid == 0) s_base = ld_acq(&g_slots[blockIdx.x]);

    // U slice into registers: 4 rows x 16 k-values
    const float* U = rg ? Uh : Uz;
    float Ureg[4][16];
    #pragma unroll
    for (int r = 0; r < 4; ++r)
        #pragma unroll
        for (int i = 0; i < 16; ++i)
            Ureg[r][i] = U[(size_t)(j0 + r) * HH + lane + 32*i];

    // h0 = 0
    for (int f = tid; f < BB*HH/4; f += 256)
        ((float4*)hs)[f] = make_float4(0.f, 0.f, 0.f, 0.f);
    __syncthreads();
    unsigned base = s_base;

    for (int t = 0; t < TT; ++t) {
        if (t > 0) {
            const float4* src = (const float4*)(g_hbuf + (size_t)((t+1)&1) * BB * HH);
            #pragma unroll
            for (int q = 0; q < 8; ++q) {
                int f = tid + q * 256;
                ((float4*)hs)[f] = __ldcg(src + f);
            }
            __syncthreads();
        }

        // early-issue projection loads for this CTA's outputs
        float wzv = 0.f, whv = 0.f; int obase = 0;
        if (tid < 64) {
            int b = tid >> 2, r = tid & 3;
            obase = (t * BB + b) * HH + j0 + r;
            wzv = __ldcg(&wz[obase]);
            whv = __ldcg(&wh[obase]);
        }

        // dot products: acc[r][b'] = sum over this lane's k of U[r][k]*h[b'][k]
        float acc[4][4] = {};
        const float* hb = &hs[bg * 4][0];
        #pragma unroll
        for (int i = 0; i < 16; ++i) {
            int k = lane + 32 * i;
            float h0v = hb[k], h1v = hb[HH + k], h2v = hb[2*HH + k], h3v = hb[3*HH + k];
            #pragma unroll
            for (int r = 0; r < 4; ++r) {
                float u = Ureg[r][i];
                acc[r][0] += u * h0v; acc[r][1] += u * h1v;
                acc[r][2] += u * h2v; acc[r][3] += u * h3v;
            }
        }
        // butterfly reduce over 32 lanes (all lanes end with full sums)
        #pragma unroll
        for (int m = 16; m >= 1; m >>= 1)
            #pragma unroll
            for (int r = 0; r < 4; ++r)
                #pragma unroll
                for (int b = 0; b < 4; ++b)
                    acc[r][b] += __shfl_xor_sync(0xffffffffu, acc[r][b], m);
        if (lane < 16)
            sdot[rg][bg * 4 + (lane & 3)][lane >> 2] = acc[lane >> 2][lane & 3];
        __syncthreads();

        if (tid < 64) {
            int b = tid >> 2, r = tid & 3;
            float z  = 1.f / (1.f + __expf(-(wzv + sdot[0][b][r])));
            float hc = whv + sdot[1][b][r];
            hc = hc > 0.f ? hc : 0.f;
            float hn = z * hs[b][j0 + r] + (1.f - z) * hc;
            g_hbuf[(size_t)(t & 1) * BB * HH + b * HH + j0 + r] = hn;
            out[obase] = hn;
        }
        __syncthreads();

        // grid barrier: monotonic slots, base-consistent across runs
        if (tid == 0) { __threadfence(); st_rel(&g_slots[blockIdx.x], base + t + 1); }
        unsigned tgt = base + t + 1;
        if (tid < NC) {
            while (ld_acq(&g_slots[tid]) < tgt) { }
        }
        __syncthreads();
    }
}

// ---------------- launch ----------------------------------------------------
extern "C" void kernel_launch(void* const* d_in, const int* in_sizes, int n_in,
                              void* d_out, int out_size) {
    const float* x   = (const float*)d_in[0];
    const float* Wh0 = (const float*)d_in[1];
    const float* bh0 = (const float*)d_in[2];
    const float* Wz0 = (const float*)d_in[3];
    const float* bz0 = (const float*)d_in[4];
    const float* Uh0 = (const float*)d_in[5];
    const float* Uz0 = (const float*)d_in[6];
    const float* Wh1 = (const float*)d_in[7];
    const float* bh1 = (const float*)d_in[8];
    const float* Wz1 = (const float*)d_in[9];
    const float* bz1 = (const float*)d_in[10];
    const float* Uh1 = (const float*)d_in[11];
    const float* Uz1 = (const float*)d_in[12];
    float* out = (float*)d_out;

    dim3 gg(MM / 64, HH / 64);
    gemm512<<<gg, 256>>>(x, 0, Wh0, bh0, 0, FF);
    gemm512<<<gg, 256>>>(x, 0, Wz0, bz0, 1, FF);
    recur<<<NC, 256>>>(Uh0, Uz0, 0, nullptr);
    gemm512<<<gg, 256>>>(nullptr, 1, Wh1, bh1, 2, HH);
    gemm512<<<gg, 256>>>(nullptr, 1, Wz1, bz1, 3, HH);
    recur<<<NC, 256>>>(Uh1, Uz1, 1, out);
}

// round 8
// speedup vs baseline: 2.0665x; 2.0665x over previous
#include <cuda_runtime.h>
#include <math.h>

#define TT 1500
#define BB 16
#define FF 440
#define HH 512
#define MM (TT*BB)      // 24000
#define NC 128          // persistent recurrence CTAs (single wave)

typedef unsigned long long ull;

// ---------------- device scratch (no allocations allowed) -------------------
__device__ float g_wh0[MM*HH];
__device__ float g_wz0[MM*HH];
__device__ float g_wh1[MM*HH];
__device__ float g_wz1[MM*HH];
__device__ float g_h1 [MM*HH];
__device__ float g_hbuf[2*BB*HH];
__device__ unsigned g_count;   // zero-init; monotonic arrivals
__device__ unsigned g_gen;     // zero-init; completed barrier generations

// ---------------- helpers ----------------------------------------------------
__device__ __forceinline__ unsigned ld_acq(const unsigned* p) {
    unsigned v;
    asm volatile("ld.acquire.gpu.u32 %0, [%1];" : "=r"(v) : "l"(p) : "memory");
    return v;
}
__device__ __forceinline__ void st_rel(unsigned* p, unsigned v) {
    asm volatile("st.release.gpu.u32 [%0], %1;" :: "l"(p), "r"(v) : "memory");
}
__device__ __forceinline__ void fma2(ull &d, ull a, ull b) {
    asm("fma.rn.f32x2 %0, %1, %2, %0;" : "+l"(d) : "l"(a), "l"(b));
}
__device__ __forceinline__ void unpack2(ull v, float &lo, float &hi) {
    asm("mov.b64 {%0, %1}, %2;" : "=f"(lo), "=f"(hi) : "l"(v));
}

// ---------------- projection GEMM: C[M,512] = A[M,K] @ W[512,K]^T + bias ----
// 64x128 tile, BK=8, 256 threads, 4x8 micro-tile.
__global__ void __launch_bounds__(256) gemm512(
    const float* __restrict__ Aext, int a_is_h1,
    const float* __restrict__ W, const float* __restrict__ bias,
    int out_sel, int K)
{
    const float* A = a_is_h1 ? g_h1 : Aext;
    float* C = (out_sel == 0) ? g_wh0 : (out_sel == 1) ? g_wz0
             : (out_sel == 2) ? g_wh1 : g_wz1;

    __shared__ __align__(16) float As[8][64];
    __shared__ __align__(16) float Bs[8][128];

    int tid = threadIdx.x;
    int m0 = blockIdx.x * 64, n0 = blockIdx.y * 128;

    int arow = tid >> 2;            // 0..63
    int akk  = (tid & 3) * 2;       // 0,2,4,6
    int brow = tid >> 1;            // 0..127
    int bkk  = (tid & 1) * 4;       // 0,4
    const float* ap = A + (size_t)(m0 + arow) * K + akk;
    const float* wp = W + (size_t)(n0 + brow) * K + bkk;

    int ty = tid >> 4, tx = tid & 15;   // rows ty*4.., cols tx*8..

    float acc[4][8] = {};
    int nkb = K / 8;
    for (int kb = 0; kb < nkb; ++kb) {
        float2 av = *(const float2*)ap;
        float4 wv = *(const float4*)wp;
        ap += 8; wp += 8;
        As[akk][arow] = av.x; As[akk+1][arow] = av.y;
        Bs[bkk+0][brow] = wv.x; Bs[bkk+1][brow] = wv.y;
        Bs[bkk+2][brow] = wv.z; Bs[bkk+3][brow] = wv.w;
        __syncthreads();
        #pragma unroll
        for (int k = 0; k < 8; ++k) {
            float4 a4  = *(const float4*)&As[k][ty*4];
            float4 b40 = *(const float4*)&Bs[k][tx*8];
            float4 b41 = *(const float4*)&Bs[k][tx*8+4];
            float a_[4] = {a4.x, a4.y, a4.z, a4.w};
            float b_[8] = {b40.x, b40.y, b40.z, b40.w, b41.x, b41.y, b41.z, b41.w};
            #pragma unroll
            for (int i = 0; i < 4; ++i)
                #pragma unroll
                for (int j = 0; j < 8; ++j)
                    acc[i][j] += a_[i] * b_[j];
        }
        __syncthreads();
    }
    float4 bia0 = *(const float4*)&bias[n0 + tx*8];
    float4 bia1 = *(const float4*)&bias[n0 + tx*8 + 4];
    #pragma unroll
    for (int i = 0; i < 4; ++i) {
        float4 o0, o1;
        o0.x = acc[i][0] + bia0.x; o0.y = acc[i][1] + bia0.y;
        o0.z = acc[i][2] + bia0.z; o0.w = acc[i][3] + bia0.w;
        o1.x = acc[i][4] + bia1.x; o1.y = acc[i][5] + bia1.y;
        o1.z = acc[i][6] + bia1.z; o1.w = acc[i][7] + bia1.w;
        float* cr = &C[(size_t)(m0 + ty*4 + i) * HH + n0 + tx*8];
        *(float4*)cr = o0;
        *(float4*)(cr + 4) = o1;
    }
}

// ---------------- persistent recurrence kernel ------------------------------
// 128 CTAs x 256 threads. CTA owns 4 output columns (both gates).
// warp w: bg = w>>1 (batch group of 4), rg = w&1 (0: z/Uz, 1: hcand/Uh).
// lane covers k-pairs k0 = lane*2 + 64*i, i<8; U slice in registers (f32x2).
__global__ void __launch_bounds__(256, 1) recur(
    const float* __restrict__ Uh, const float* __restrict__ Uz,
    int layer, float* __restrict__ out_ext)
{
    const float* wh = layer ? g_wh1 : g_wh0;
    const float* wz = layer ? g_wz1 : g_wz0;
    float* out = out_ext ? out_ext : g_h1;

    __shared__ __align__(16) float hs[BB][HH];   // 32 KB
    __shared__ float sdot[2][BB][4];
    __shared__ unsigned s_base;

    int tid  = threadIdx.x;
    int w    = tid >> 5, lane = tid & 31;
    int bg   = w >> 1,   rg   = w & 1;
    int j0   = blockIdx.x * 4;

    if (tid == 0) s_base = ld_acq(&g_gen);

    // U slice into registers: 4 rows x 8 k-pairs (f32x2)
    const float* U = rg ? Uh : Uz;
    ull Ureg[4][8];
    int k0 = lane * 2;
    #pragma unroll
    for (int r = 0; r < 4; ++r)
        #pragma unroll
        for (int i = 0; i < 8; ++i)
            Ureg[r][i] = *(const ull*)&U[(size_t)(j0 + r) * HH + k0 + 64*i];

    // h0 = 0
    for (int f = tid; f < BB*HH/4; f += 256)
        ((float4*)hs)[f] = make_float4(0.f, 0.f, 0.f, 0.f);
    __syncthreads();
    unsigned base = s_base;

    // per-thread gate assignment (threads 0..63)
    int gb = tid >> 2, gr = tid & 3;
    float wzv = 0.f, whv = 0.f;
    int obase = (0 * BB + gb) * HH + j0 + gr;
    if (tid < 64) {
        wzv = __ldcg(&wz[obase]);
        whv = __ldcg(&wh[obase]);
    }

    for (int t = 0; t < TT; ++t) {
        if (t > 0) {
            // wait for barrier generation base+t (h_{t-1} published)
            if (tid == 0) {
                unsigned tgt = base + (unsigned)t;
                while ((int)(ld_acq(&g_gen) - tgt) < 0) { }
            }
            __syncthreads();
            const float4* src = (const float4*)(g_hbuf + (size_t)((t+1)&1) * BB * HH);
            #pragma unroll
            for (int q = 0; q < 8; ++q) {
                int f = tid + q * 256;
                ((float4*)hs)[f] = __ldcg(src + f);
            }
            __syncthreads();
        }

        // dot products: acc2[r][b'] over this lane's k-pairs (packed f32x2)
        ull acc2[4][4];
        #pragma unroll
        for (int r = 0; r < 4; ++r)
            #pragma unroll
            for (int b = 0; b < 4; ++b) acc2[r][b] = 0ull;

        const float* hb = &hs[bg * 4][0];
        #pragma unroll
        for (int i = 0; i < 8; ++i) {
            int k = k0 + 64 * i;
            ull h0v = *(const ull*)&hb[k];
            ull h1v = *(const ull*)&hb[HH + k];
            ull h2v = *(const ull*)&hb[2*HH + k];
            ull h3v = *(const ull*)&hb[3*HH + k];
            #pragma unroll
            for (int r = 0; r < 4; ++r) {
                fma2(acc2[r][0], Ureg[r][i], h0v);
                fma2(acc2[r][1], Ureg[r][i], h1v);
                fma2(acc2[r][2], Ureg[r][i], h2v);
                fma2(acc2[r][3], Ureg[r][i], h3v);
            }
        }
        float acc[4][4];
        #pragma unroll
        for (int r = 0; r < 4; ++r)
            #pragma unroll
            for (int b = 0; b < 4; ++b) {
                float lo, hi; unpack2(acc2[r][b], lo, hi);
                acc[r][b] = lo + hi;
            }
        // butterfly reduce over 32 lanes
        #pragma unroll
        for (int m = 16; m >= 1; m >>= 1)
            #pragma unroll
            for (int r = 0; r < 4; ++r)
                #pragma unroll
                for (int b = 0; b < 4; ++b)
                    acc[r][b] += __shfl_xor_sync(0xffffffffu, acc[r][b], m);
        if (lane < 16)
            sdot[rg][bg * 4 + (lane & 3)][lane >> 2] = acc[lane >> 2][lane & 3];
        __syncthreads();

        if (tid < 64) {
            float z  = 1.f / (1.f + __expf(-(wzv + sdot[0][gb][gr])));
            float hc = whv + sdot[1][gb][gr];
            hc = hc > 0.f ? hc : 0.f;
            float hn = z * hs[gb][j0 + gr] + (1.f - z) * hc;
            g_hbuf[(size_t)(t & 1) * BB * HH + gb * HH + j0 + gr] = hn;
            out[obase] = hn;
            // prefetch next step's projections (overlaps barrier wait)
            if (t + 1 < TT) {
                obase += BB * HH;
                wzv = __ldcg(&wz[obase]);
                whv = __ldcg(&wh[obase]);
            }
        }
        __syncthreads();

        // arrive: single counter; last CTA publishes generation (broadcast flag)
        if (tid == 0) {
            __threadfence();
            unsigned old = atomicAdd(&g_count, 1u);
            if (old + 1u == (base + (unsigned)t + 1u) * NC)
                st_rel(&g_gen, base + (unsigned)t + 1u);
        }
    }
}

// ---------------- launch ----------------------------------------------------
extern "C" void kernel_launch(void* const* d_in, const int* in_sizes, int n_in,
                              void* d_out, int out_size) {
    const float* x   = (const float*)d_in[0];
    const float* Wh0 = (const float*)d_in[1];
    const float* bh0 = (const float*)d_in[2];
    const float* Wz0 = (const float*)d_in[3];
    const float* bz0 = (const float*)d_in[4];
    const float* Uh0 = (const float*)d_in[5];
    const float* Uz0 = (const float*)d_in[6];
    const float* Wh1 = (const float*)d_in[7];
    const float* bh1 = (const float*)d_in[8];
    const float* Wz1 = (const float*)d_in[9];
    const float* bz1 = (const float*)d_in[10];
    const float* Uh1 = (const float*)d_in[11];
    const float* Uz1 = (const float*)d_in[12];
    float* out = (float*)d_out;

    dim3 gg(MM / 64, HH / 128);
    gemm512<<<gg, 256>>>(x, 0, Wh0, bh0, 0, FF);
    gemm512<<<gg, 256>>>(x, 0, Wz0, bz0, 1, FF);
    recur<<<NC, 256>>>(Uh0, Uz0, 0, nullptr);
    gemm512<<<gg, 256>>>(nullptr, 1, Wh1, bh1, 2, HH);
    gemm512<<<gg, 256>>>(nullptr, 1, Wz1, bz1, 3, HH);
    recur<<<NC, 256>>>(Uh1, Uz1, 1, out);
}